// round 6
// baseline (speedup 1.0000x reference)
#include <cuda_runtime.h>
#include <cstdint>

#define NN 50000
#define NE 500000
#define HH 128

// ---------------- scratch (device globals; no cudaMalloc allowed) ----------------
__device__ float g_U[NN * HH];
__device__ float g_V[NN * HH];
__device__ float g_WE[(long)NE * HH];   // holds ea@W1c+b1, then overwritten with relu(h)
__device__ float g_S[NN * HH];          // segment sum of relu(h)
__device__ float g_INTRA[NN * HH];
__device__ float g_HID[NN * 2 * HH];
__device__ float g_XA[NN * HH];
__device__ float g_XB[NN * HH];
__device__ float g_POS[NN * 3];
__device__ float g_POSACC[NN * 3];
__device__ float g_W[NE];               // per-edge scalar w
__device__ float g_DEG[NN];
__device__ float g_DINV[NN];
__device__ float g_BMASK[NN];
__device__ float g_C[HH * 256];         // W2 @ aW1
__device__ float g_D[256];              // b2 @ aW1 + ab1
__device__ int   g_SRC[NE];
__device__ int   g_DST[NE];

// -------- index normalization: handles harness storing edge_index as int32 OR int64
__global__ void convert_idx(const int* __restrict__ ei32, int* __restrict__ SRC,
                            int* __restrict__ DST)
{
    // int64 little-endian values < 2^31 have zero high words at odd int32 slots.
    bool is64 = (ei32[1] == 0 && ei32[3] == 0 && ei32[5] == 0 && ei32[7] == 0);
    int e = blockIdx.x * blockDim.x + threadIdx.x;
    if (e >= NE) return;
    if (is64) {
        const long long* e64 = (const long long*)ei32;
        SRC[e] = (int)e64[e];
        DST[e] = (int)e64[NE + e];
    } else {
        SRC[e] = ei32[e];
        DST[e] = ei32[NE + e];
    }
}

// ---------------- generic 64x64x16 fp32 GEMM, 256 threads, 4x4 per thread --------
// C[m,j] = (sum_k A[m,k] * B[k,j]) * rowscale[m] + bias[j]*rowmask[m]; optional relu.
// If A2 != null: logical A row = concat(A[m,0:128], A2[m,0:128]) (K must be 256).
__global__ void __launch_bounds__(256) gemm64(
    const float* __restrict__ A, const float* __restrict__ A2,
    const float* __restrict__ B, const float* __restrict__ bias,
    float* __restrict__ Cout, int M, int K, int Ncols,
    int reluFlag, const float* __restrict__ rowscale, const float* __restrict__ rowmask)
{
    __shared__ float As[16][64];
    __shared__ float Bs[16][64];
    const int bm = blockIdx.y * 64;
    const int bn = blockIdx.x * 64;
    const int tid = threadIdx.x;
    const int ty = tid >> 4, tx = tid & 15;
    const int am = tid >> 2, ak = (tid & 3) << 2;
    const int bk = tid >> 4, bj = (tid & 15) << 2;

    float acc[4][4];
#pragma unroll
    for (int i = 0; i < 4; i++)
#pragma unroll
        for (int j = 0; j < 4; j++) acc[i][j] = 0.f;

    for (int k0 = 0; k0 < K; k0 += 16) {
        float4 av = make_float4(0.f, 0.f, 0.f, 0.f);
        int grow = bm + am;
        if (grow < M) {
            int gk = k0 + ak;
            const float* src;
            if (A2 != nullptr) {
                src = (gk < HH) ? (A + (long)grow * HH + gk)
                                : (A2 + (long)grow * HH + (gk - HH));
            } else {
                src = A + (long)grow * K + gk;
            }
            av = *(const float4*)src;
        }
        As[ak + 0][am] = av.x; As[ak + 1][am] = av.y;
        As[ak + 2][am] = av.z; As[ak + 3][am] = av.w;
        float4 bv = *(const float4*)(B + (long)(k0 + bk) * Ncols + bn + bj);
        *(float4*)&Bs[bk][bj] = bv;
        __syncthreads();
#pragma unroll
        for (int kk = 0; kk < 16; kk++) {
            float4 a = *(const float4*)&As[kk][ty << 2];
            float4 b = *(const float4*)&Bs[kk][tx << 2];
            float ar[4] = {a.x, a.y, a.z, a.w};
            float br[4] = {b.x, b.y, b.z, b.w};
#pragma unroll
            for (int i = 0; i < 4; i++)
#pragma unroll
                for (int j = 0; j < 4; j++) acc[i][j] += ar[i] * br[j];
        }
        __syncthreads();
    }
#pragma unroll
    for (int i = 0; i < 4; i++) {
        int row = bm + (ty << 2) + i;
        if (row >= M) continue;
        float rs = rowscale ? rowscale[row] : 1.f;
        float rm = rowmask ? rowmask[row] : 1.f;
        float4 o;
        float* op = (float*)&o;
#pragma unroll
        for (int j = 0; j < 4; j++) {
            int col = bn + (tx << 2) + j;
            float v = acc[i][j] * rs;
            if (bias) v += bias[col] * rm;
            if (reluFlag) v = fmaxf(v, 0.f);
            op[j] = v;
        }
        *(float4*)(Cout + (long)row * Ncols + bn + (tx << 2)) = o;
    }
}

// -------- fused edge-acc GEMM: w[e] = sum_j relu(R[e]@C + D)[j]*aW2[j] ------------
// One block handles 64 edges x all 256 cols (K=128); no atomics, deterministic.
// Per-thread: 4 rows x 16 cols, columns interleaved (tx*4 + 64*b) so shared loads
// stay stride-16B conflict-free.
__global__ void __launch_bounds__(256) edge_acc_kernel(
    const float* __restrict__ R, const float* __restrict__ C,
    const float* __restrict__ D, const float* __restrict__ aW2,
    float* __restrict__ Wout)
{
    __shared__ float As[16][64];
    __shared__ float Bs[16][256];
    __shared__ float red[64][17];
    const int bm = blockIdx.x * 64;
    const int tid = threadIdx.x;
    const int ty = tid >> 4, tx = tid & 15;
    const int am = tid >> 2, ak = (tid & 3) << 2;
    const int bk = tid >> 4, bj = (tid & 15) << 2;

    float acc[4][16];
#pragma unroll
    for (int i = 0; i < 4; i++)
#pragma unroll
        for (int j = 0; j < 16; j++) acc[i][j] = 0.f;

    for (int k0 = 0; k0 < 128; k0 += 16) {
        float4 av = make_float4(0.f, 0.f, 0.f, 0.f);
        int grow = bm + am;
        if (grow < NE) av = *(const float4*)(R + (long)grow * HH + k0 + ak);
        As[ak + 0][am] = av.x; As[ak + 1][am] = av.y;
        As[ak + 2][am] = av.z; As[ak + 3][am] = av.w;
#pragma unroll
        for (int b = 0; b < 4; b++) {
            float4 bv = *(const float4*)(C + (long)(k0 + bk) * 256 + b * 64 + bj);
            *(float4*)&Bs[bk][b * 64 + bj] = bv;
        }
        __syncthreads();
#pragma unroll
        for (int kk = 0; kk < 16; kk++) {
            float4 a = *(const float4*)&As[kk][ty << 2];
            float ar[4] = {a.x, a.y, a.z, a.w};
#pragma unroll
            for (int b = 0; b < 4; b++) {
                float4 bb = *(const float4*)&Bs[kk][b * 64 + (tx << 2)];
                float br[4] = {bb.x, bb.y, bb.z, bb.w};
#pragma unroll
                for (int i = 0; i < 4; i++)
#pragma unroll
                    for (int j = 0; j < 4; j++)
                        acc[i][b * 4 + j] += ar[i] * br[j];
            }
        }
        __syncthreads();
    }
    // epilogue: relu(acc + D) * aW2, reduce over this thread's 16 cols
#pragma unroll
    for (int i = 0; i < 4; i++) {
        float s = 0.f;
#pragma unroll
        for (int b = 0; b < 4; b++)
#pragma unroll
            for (int j = 0; j < 4; j++) {
                int col = b * 64 + (tx << 2) + j;
                s += fmaxf(acc[i][b * 4 + j] + D[col], 0.f) * aW2[col];
            }
        red[(ty << 2) + i][tx] = s;
    }
    __syncthreads();
    if (tid < 64) {
        float t = 0.f;
#pragma unroll
        for (int q = 0; q < 16; q++) t += red[tid][q];
        int row = bm + tid;
        if (row < NE) Wout[row] = t;
    }
}

// ---------------- per-edge relu-hidden + segment sum of relu(h) -------------------
__global__ void edge_r_kernel(const int* __restrict__ SRC, const int* __restrict__ DST,
                              float* __restrict__ WE,
                              const float* __restrict__ U, const float* __restrict__ V,
                              float* __restrict__ S, int doS)
{
    long idx = (long)blockIdx.x * blockDim.x + threadIdx.x;
    long e = idx >> 5;
    int lane = (int)(idx & 31);
    if (e >= NE) return;
    int src = SRC[e];
    int dst = DST[e];
    const float4 u = *(const float4*)(U + (long)dst * HH + lane * 4);
    const float4 v = *(const float4*)(V + (long)src * HH + lane * 4);
    float4 w = *(float4*)(WE + e * HH + lane * 4);
    w.x = fmaxf(u.x + v.x + w.x, 0.f);
    w.y = fmaxf(u.y + v.y + w.y, 0.f);
    w.z = fmaxf(u.z + v.z + w.z, 0.f);
    w.w = fmaxf(u.w + v.w + w.w, 0.f);
    *(float4*)(WE + e * HH + lane * 4) = w;
    if (doS) {
        float* sp = S + (long)dst * HH + lane * 4;
        atomicAdd(sp + 0, w.x);
        atomicAdd(sp + 1, w.y);
        atomicAdd(sp + 2, w.z);
        atomicAdd(sp + 3, w.w);
    }
}

// ---------------- small per-layer prep: C = W2@aW1, D = b2@aW1 + ab1 --------------
__global__ void prep_kernel(const float* __restrict__ W2, const float* __restrict__ aW1,
                            const float* __restrict__ b2, const float* __restrict__ ab1,
                            float* __restrict__ C, float* __restrict__ D)
{
    int j = threadIdx.x;   // 0..255
    int k = blockIdx.x;    // 0..128
    if (k < 128) {
        float s = 0.f;
#pragma unroll 8
        for (int t = 0; t < 128; t++) s += W2[k * 128 + t] * aW1[t * 256 + j];
        C[k * 256 + j] = s;
    } else {
        float s = ab1[j];
#pragma unroll 8
        for (int t = 0; t < 128; t++) s += b2[t] * aW1[t * 256 + j];
        D[j] = s;
    }
}

// ---------------- degree / denom -------------------------------------------------
__global__ void deg_kernel(const int* __restrict__ DST, float* __restrict__ DEG)
{
    int e = blockIdx.x * blockDim.x + threadIdx.x;
    if (e < NE) atomicAdd(&DEG[DST[e]], 1.f);
}

__global__ void dinv_kernel(const float* __restrict__ DEG, float* __restrict__ DINV,
                            float* __restrict__ BM)
{
    int n = blockIdx.x * blockDim.x + threadIdx.x;
    if (n >= NN) return;
    float d = DEG[n];
    DINV[n] = 1.f / fmaxf(d, 1.f);
    BM[n] = (d > 0.f) ? 1.f : 0.f;
}

// ---------------- per-edge equivariant pos accumulation --------------------------
__global__ void pos_edge_kernel(const int* __restrict__ SRC, const int* __restrict__ DST,
                                const float* __restrict__ W,
                                const float* __restrict__ ab2, const float* __restrict__ POS,
                                float* __restrict__ PACC)
{
    int e = blockIdx.x * blockDim.x + threadIdx.x;
    if (e >= NE) return;
    int src = SRC[e], dst = DST[e];
    float w = W[e] + ab2[0];
    float rx = POS[src * 3 + 0] - POS[dst * 3 + 0];
    float ry = POS[src * 3 + 1] - POS[dst * 3 + 1];
    float rz = POS[src * 3 + 2] - POS[dst * 3 + 2];
    float dist = sqrtf(rx * rx + ry * ry + rz * rz);
    float s = w / dist;
    atomicAdd(&PACC[dst * 3 + 0], s * rx);
    atomicAdd(&PACC[dst * 3 + 1], s * ry);
    atomicAdd(&PACC[dst * 3 + 2], s * rz);
}

__global__ void pos_apply_kernel(float* __restrict__ POS, const float* __restrict__ PACC,
                                 const float* __restrict__ DINV, float* __restrict__ outp)
{
    int n = blockIdx.x * blockDim.x + threadIdx.x;
    if (n >= NN) return;
    float di = DINV[n];
#pragma unroll
    for (int i = 0; i < 3; i++) {
        float v = POS[n * 3 + i] + PACC[n * 3 + i] * di;
        POS[n * 3 + i] = v;
        if (outp) outp[n * 3 + i] = v;
    }
}

// ---------------- host ------------------------------------------------------------
extern "C" void kernel_launch(void* const* d_in, const int* in_sizes, int n_in,
                              void* d_out, int out_size)
{
    const float* x        = (const float*)d_in[0];
    const int*   ei32     = (const int*)d_in[1];
    const float* ea       = (const float*)d_in[2];
    const float* pos      = (const float*)d_in[3];
    const float* mW1      = (const float*)d_in[4];
    const float* mb1      = (const float*)d_in[5];
    const float* mW2      = (const float*)d_in[6];
    const float* mb2      = (const float*)d_in[7];
    const float* aW1      = (const float*)d_in[8];
    const float* ab1      = (const float*)d_in[9];
    const float* aW2      = (const float*)d_in[10];
    const float* ab2      = (const float*)d_in[11];
    const float* nW1      = (const float*)d_in[12];
    const float* nb1      = (const float*)d_in[13];
    const float* nW2      = (const float*)d_in[14];
    const float* nb2      = (const float*)d_in[15];
    float* outp = (float*)d_out;

    float *pU, *pV, *pWE, *pS, *pINTRA, *pHID, *pXA, *pXB, *pPOS, *pPACC, *pW;
    float *pDEG, *pDINV, *pBM, *pC, *pD;
    int *pSRC, *pDST;
    cudaGetSymbolAddress((void**)&pU, g_U);
    cudaGetSymbolAddress((void**)&pV, g_V);
    cudaGetSymbolAddress((void**)&pWE, g_WE);
    cudaGetSymbolAddress((void**)&pS, g_S);
    cudaGetSymbolAddress((void**)&pINTRA, g_INTRA);
    cudaGetSymbolAddress((void**)&pHID, g_HID);
    cudaGetSymbolAddress((void**)&pXA, g_XA);
    cudaGetSymbolAddress((void**)&pXB, g_XB);
    cudaGetSymbolAddress((void**)&pPOS, g_POS);
    cudaGetSymbolAddress((void**)&pPACC, g_POSACC);
    cudaGetSymbolAddress((void**)&pW, g_W);
    cudaGetSymbolAddress((void**)&pDEG, g_DEG);
    cudaGetSymbolAddress((void**)&pDINV, g_DINV);
    cudaGetSymbolAddress((void**)&pBM, g_BMASK);
    cudaGetSymbolAddress((void**)&pC, g_C);
    cudaGetSymbolAddress((void**)&pD, g_D);
    cudaGetSymbolAddress((void**)&pSRC, g_SRC);
    cudaGetSymbolAddress((void**)&pDST, g_DST);

    cudaMemcpyAsync(pPOS, pos, (size_t)NN * 3 * sizeof(float), cudaMemcpyDeviceToDevice);
    convert_idx<<<(NE + 255) / 256, 256>>>(ei32, pSRC, pDST);
    cudaMemsetAsync(pDEG, 0, (size_t)NN * sizeof(float));
    deg_kernel<<<(NE + 255) / 256, 256>>>(pDST, pDEG);
    dinv_kernel<<<(NN + 255) / 256, 256>>>(pDEG, pDINV, pBM);

    const float* xc = x;
    float* xn = pXA;

    for (int l = 0; l < 3; l++) {
        const int last = (l == 2);
        const float* mW1l = mW1 + (long)l * 384 * 128;
        const float* mb1l = mb1 + (long)l * 128;
        const float* mW2l = mW2 + (long)l * 128 * 128;
        const float* mb2l = mb2 + (long)l * 128;
        const float* aW1l = aW1 + (long)l * 128 * 256;
        const float* ab1l = ab1 + (long)l * 256;
        const float* aW2l = aW2 + (long)l * 256;
        const float* ab2l = ab2 + (long)l;
        const float* nW1l = nW1 + (long)l * 256 * 256;
        const float* nb1l = nb1 + (long)l * 256;
        const float* nW2l = nW2 + (long)l * 256 * 128;
        const float* nb2l = nb2 + (long)l * 128;

        if (!last) cudaMemsetAsync(pS, 0, (size_t)NN * HH * sizeof(float));
        cudaMemsetAsync(pPACC, 0, (size_t)NN * 3 * sizeof(float));

        prep_kernel<<<129, 256>>>(mW2l, aW1l, mb2l, ab1l, pC, pD);

        dim3 gN(2, (NN + 63) / 64);
        gemm64<<<gN, 256>>>(xc, nullptr, mW1l, nullptr, pU, NN, 128, 128, 0, nullptr, nullptr);
        gemm64<<<gN, 256>>>(xc, nullptr, mW1l + 128 * 128, nullptr, pV, NN, 128, 128, 0, nullptr, nullptr);

        dim3 gE(2, (NE + 63) / 64);
        gemm64<<<gE, 256>>>(ea, nullptr, mW1l + 256 * 128, mb1l, pWE, NE, 128, 128, 0, nullptr, nullptr);

        edge_r_kernel<<<(int)(((long)NE * 32 + 255) / 256), 256>>>(pSRC, pDST, pWE, pU, pV, pS, last ? 0 : 1);

        edge_acc_kernel<<<(NE + 63) / 64, 256>>>(pWE, pC, pD, aW2l, pW);

        pos_edge_kernel<<<(NE + 255) / 256, 256>>>(pSRC, pDST, pW, ab2l, pPOS, pPACC);
        pos_apply_kernel<<<(NN + 255) / 256, 256>>>(pPOS, pPACC, pDINV, last ? outp : nullptr);

        if (!last) {
            gemm64<<<gN, 256>>>(pS, nullptr, mW2l, mb2l, pINTRA, NN, 128, 128, 0, pDINV, pBM);
            dim3 gH(4, (NN + 63) / 64);
            gemm64<<<gH, 256>>>(xc, pINTRA, nW1l, nb1l, pHID, NN, 256, 256, 1, nullptr, nullptr);
            gemm64<<<gN, 256>>>(pHID, nullptr, nW2l, nb2l, xn, NN, 256, 128, 0, nullptr, nullptr);
            xc = xn;
            xn = (xn == pXA) ? pXB : pXA;
        }
    }
}